// round 6
// baseline (speedup 1.0000x reference)
#include <cuda_runtime.h>
#include <cuda_bf16.h>

// PackedAvgPool1d — fused persistent streaming kernel.
//   Grid = 5 blocks/SM (occupancy-exact). Each block builds the prefix tables
//   ONCE (warp-parallel shfl scan), then grid-strides over row-groups:
//   thread = (row, 2 column-chunks): 4 front-batched LDG.128 + 2 STG.128.
// DIM = 768 -> 192 float4 per row; chunks at c and c+96.

#define POOL_D4   192
#define MAX_BATCH 1024
#define FULLMASK  0xFFFFFFFFu

__global__ void __launch_bounds__(384) pool_fused_kernel(
    const float4* __restrict__ x,
    const int*    __restrict__ seq_lens,
    const int*    __restrict__ pK,
    const int*    __restrict__ pS,
    float4*       __restrict__ out,
    int batch, int n_rows)
{
    __shared__ int s_xcu[MAX_BATCH + 1];
    __shared__ int s_ycu[MAX_BATCH + 1];
    __shared__ int s_KS[2];

    const int ltid = threadIdx.y * 96 + threadIdx.x;

    // ---- prologue (once per block): warp 0 builds prefix tables ----
    if (ltid < 32) {
        const int lane = ltid;
        const int K = pK ? __ldg(pK) : 2;
        const int S = pS ? __ldg(pS) : 2;
        if (lane == 0) { s_KS[0] = K; s_KS[1] = S; s_xcu[0] = 0; s_ycu[0] = 0; }
        int xoff = 0, yoff = 0;
        for (int chunk = 0; chunk < batch; chunk += 32) {
            const int i = chunk + lane;
            int L = (i < batch) ? __ldg(&seq_lens[i]) : 0;
            int yl = 0;
            if (L > 0) {
                int num = L - K; if (num < 0) num = 0;
                yl = (num + S - 1) / S + 1;
            }
            int xs = L, ys = yl;
            #pragma unroll
            for (int d = 1; d < 32; d <<= 1) {
                const int nx = __shfl_up_sync(FULLMASK, xs, d);
                const int ny = __shfl_up_sync(FULLMASK, ys, d);
                if (lane >= d) { xs += nx; ys += ny; }
            }
            if (i < batch) {
                s_xcu[i + 1] = xoff + xs;
                s_ycu[i + 1] = yoff + ys;
            }
            xoff += __shfl_sync(FULLMASK, xs, 31);
            yoff += __shfl_sync(FULLMASK, ys, 31);
        }
    }
    __syncthreads();

    const int K = s_KS[0];
    const int S = s_KS[1];
    const int c = threadIdx.x;              // 0..95, chunks at c and c+96
    const int nGroups = (n_rows + 3) / 4;

    for (int g = blockIdx.x; g < nGroups; g += gridDim.x) {
        const int row = g * 4 + threadIdx.y;
        if (row >= n_rows) continue;

        // Binary search: largest b with y_cu[b] <= row (LDS broadcasts).
        int lo = 0, hi = batch;
        while (hi - lo > 1) {
            const int mid = (lo + hi) >> 1;
            if (s_ycu[mid] <= row) lo = mid; else hi = mid;
        }
        const int b    = lo;
        const int j    = row - s_ycu[b];
        const int base = s_xcu[b];
        const int L    = s_xcu[b + 1] - base;
        const int p0   = j * S;
        int cnt = L - p0; if (cnt > K) cnt = K; if (cnt < 1) cnt = 1;

        const size_t sbase = (size_t)(base + p0) * POOL_D4 + c;
        // Front-batched independent loads (predicate depends only on indices):
        float4 a0 = __ldcs(&x[sbase]);
        float4 a1 = __ldcs(&x[sbase + 96]);

        if (cnt >= 2) {
            float4 b0 = __ldcs(&x[sbase + POOL_D4]);
            float4 b1 = __ldcs(&x[sbase + POOL_D4 + 96]);
            if (cnt == 2) {
                a0.x = (a0.x + b0.x) * 0.5f; a0.y = (a0.y + b0.y) * 0.5f;
                a0.z = (a0.z + b0.z) * 0.5f; a0.w = (a0.w + b0.w) * 0.5f;
                a1.x = (a1.x + b1.x) * 0.5f; a1.y = (a1.y + b1.y) * 0.5f;
                a1.z = (a1.z + b1.z) * 0.5f; a1.w = (a1.w + b1.w) * 0.5f;
            } else {                        // general K fallback (cnt > 2)
                a0.x += b0.x; a0.y += b0.y; a0.z += b0.z; a0.w += b0.w;
                a1.x += b1.x; a1.y += b1.y; a1.z += b1.z; a1.w += b1.w;
                for (int k = 2; k < cnt; ++k) {
                    const float4 v0 = __ldcs(&x[sbase + (size_t)k * POOL_D4]);
                    const float4 v1 = __ldcs(&x[sbase + (size_t)k * POOL_D4 + 96]);
                    a0.x += v0.x; a0.y += v0.y; a0.z += v0.z; a0.w += v0.w;
                    a1.x += v1.x; a1.y += v1.y; a1.z += v1.z; a1.w += v1.w;
                }
                const float inv = 1.0f / (float)cnt;
                a0.x *= inv; a0.y *= inv; a0.z *= inv; a0.w *= inv;
                a1.x *= inv; a1.y *= inv; a1.z *= inv; a1.w *= inv;
            }
        }

        const size_t obase = (size_t)row * POOL_D4 + c;
        __stcs(&out[obase], a0);
        __stcs(&out[obase + 96], a1);
    }
}

extern "C" void kernel_launch(void* const* d_in, const int* in_sizes, int n_in,
                              void* d_out, int out_size)
{
    const float4* x        = (const float4*)d_in[0];
    const int*    seq_lens = (const int*)d_in[1];
    const int*    pK       = (n_in >= 3) ? (const int*)d_in[2] : nullptr;
    const int*    pS       = (n_in >= 4) ? (const int*)d_in[3] : nullptr;
    float4*       out      = (float4*)d_out;

    const int batch  = in_sizes[1];
    const int n_rows = out_size / 768;
    if (n_rows <= 0) return;

    dim3 blk(96, 4);
    const int nGroups = (n_rows + 3) / 4;
    int grid = 148 * 5;                      // occupancy-exact persistent grid
    if (grid > nGroups) grid = nGroups;
    pool_fused_kernel<<<grid, blk>>>(x, seq_lens, pK, pS, out, batch, n_rows);
}

// round 7
// speedup vs baseline: 1.0666x; 1.0666x over previous
#include <cuda_runtime.h>
#include <cuda_bf16.h>

// PackedAvgPool1d — fused streaming kernel, warp-local index prologue.
//   blockDim = 384 flat; 4 rows per block, 3 warps per row (96 float4 cols,
//   2 chunks of 32 per thread at c and c+96).
//   Fast path (batch <= 32): lane i holds seq_lens[i]; inclusive shfl-scan of
//   x/y prefixes in registers; row->batch via one ballot+popc; no smem/syncs.
//   Fallback (batch > 32): block-shared prefix tables + binary search.
// DIM = 768 -> 192 float4 per row.

#define POOL_D4   192
#define MAX_BATCH 1024
#define FULLMASK  0xFFFFFFFFu

__global__ void __launch_bounds__(384) pool_fused_kernel(
    const float4* __restrict__ x,
    const int*    __restrict__ seq_lens,
    const int*    __restrict__ pK,
    const int*    __restrict__ pS,
    float4*       __restrict__ out,
    int batch, int n_rows)
{
    __shared__ int s_xcu[MAX_BATCH + 1];
    __shared__ int s_ycu[MAX_BATCH + 1];

    const int tid  = threadIdx.x;
    const int lane = tid & 31;
    const int warp = tid >> 5;

    const int K = pK ? __ldg(pK) : 2;
    const int S = pS ? __ldg(pS) : 2;

    const int row_in_blk = warp / 3;                 // 0..3
    const int c          = (warp % 3) * 32 + lane;   // 0..95
    const int row        = blockIdx.x * 4 + row_in_blk;

    int base, Lb, j;                                 // per-row indexing results

    if (batch <= 32) {
        // ---- warp-local prologue: no smem, no block sync ----
        int L = (lane < batch) ? __ldg(&seq_lens[lane]) : 0;
        int yl = 0;
        if (L > 0) {
            int num = L - K; if (num < 0) num = 0;
            yl = (num + S - 1) / S + 1;
        }
        int xs = L, ys = yl;                          // inclusive scans
        #pragma unroll
        for (int d = 1; d < 32; d <<= 1) {
            const int nx = __shfl_up_sync(FULLMASK, xs, d);
            const int ny = __shfl_up_sync(FULLMASK, ys, d);
            if (lane >= d) { xs += nx; ys += ny; }
        }
        if (row >= n_rows) return;
        // largest b with y_cu[b] <= row:  b = popc(ballot(y_cu[lane+1] <= row))
        const unsigned m = __ballot_sync(FULLMASK, ys <= row);
        const int b = __popc(m);
        const int ybase = (b > 0) ? __shfl_sync(FULLMASK, ys, b - 1) : 0;
        base = (b > 0) ? __shfl_sync(FULLMASK, xs, b - 1) : 0;
        Lb   = __shfl_sync(FULLMASK, L, b);
        j    = row - ybase;
    } else {
        // ---- fallback: block-shared prefix tables (batch > 32) ----
        if (warp == 0) {
            int xoff = 0, yoff = 0;
            if (lane == 0) { s_xcu[0] = 0; s_ycu[0] = 0; }
            for (int chunk = 0; chunk < batch; chunk += 32) {
                const int i = chunk + lane;
                int L = (i < batch) ? __ldg(&seq_lens[i]) : 0;
                int yl = 0;
                if (L > 0) {
                    int num = L - K; if (num < 0) num = 0;
                    yl = (num + S - 1) / S + 1;
                }
                int xs = L, ys = yl;
                #pragma unroll
                for (int d = 1; d < 32; d <<= 1) {
                    const int nx = __shfl_up_sync(FULLMASK, xs, d);
                    const int ny = __shfl_up_sync(FULLMASK, ys, d);
                    if (lane >= d) { xs += nx; ys += ny; }
                }
                if (i < batch) { s_xcu[i + 1] = xoff + xs; s_ycu[i + 1] = yoff + ys; }
                xoff += __shfl_sync(FULLMASK, xs, 31);
                yoff += __shfl_sync(FULLMASK, ys, 31);
            }
        }
        __syncthreads();
        if (row >= n_rows) return;
        int lo = 0, hi = batch;
        while (hi - lo > 1) {
            const int mid = (lo + hi) >> 1;
            if (s_ycu[mid] <= row) lo = mid; else hi = mid;
        }
        base = s_xcu[lo];
        Lb   = s_xcu[lo + 1] - base;
        j    = row - s_ycu[lo];
    }

    const int p0 = j * S;
    int cnt = Lb - p0; if (cnt > K) cnt = K; if (cnt < 1) cnt = 1;

    const size_t sbase = (size_t)(base + p0) * POOL_D4 + c;
    // Front-batched independent loads (predicate depends only on indices):
    float4 a0 = __ldcs(&x[sbase]);
    float4 a1 = __ldcs(&x[sbase + 96]);

    if (cnt >= 2) {
        float4 b0 = __ldcs(&x[sbase + POOL_D4]);
        float4 b1 = __ldcs(&x[sbase + POOL_D4 + 96]);
        if (cnt == 2) {
            a0.x = (a0.x + b0.x) * 0.5f; a0.y = (a0.y + b0.y) * 0.5f;
            a0.z = (a0.z + b0.z) * 0.5f; a0.w = (a0.w + b0.w) * 0.5f;
            a1.x = (a1.x + b1.x) * 0.5f; a1.y = (a1.y + b1.y) * 0.5f;
            a1.z = (a1.z + b1.z) * 0.5f; a1.w = (a1.w + b1.w) * 0.5f;
        } else {                          // general K fallback (cnt > 2)
            a0.x += b0.x; a0.y += b0.y; a0.z += b0.z; a0.w += b0.w;
            a1.x += b1.x; a1.y += b1.y; a1.z += b1.z; a1.w += b1.w;
            for (int k = 2; k < cnt; ++k) {
                const float4 v0 = __ldcs(&x[sbase + (size_t)k * POOL_D4]);
                const float4 v1 = __ldcs(&x[sbase + (size_t)k * POOL_D4 + 96]);
                a0.x += v0.x; a0.y += v0.y; a0.z += v0.z; a0.w += v0.w;
                a1.x += v1.x; a1.y += v1.y; a1.z += v1.z; a1.w += v1.w;
            }
            const float inv = 1.0f / (float)cnt;
            a0.x *= inv; a0.y *= inv; a0.z *= inv; a0.w *= inv;
            a1.x *= inv; a1.y *= inv; a1.z *= inv; a1.w *= inv;
        }
    }

    const size_t obase = (size_t)row * POOL_D4 + c;
    __stcs(&out[obase], a0);
    __stcs(&out[obase + 96], a1);
}

extern "C" void kernel_launch(void* const* d_in, const int* in_sizes, int n_in,
                              void* d_out, int out_size)
{
    const float4* x        = (const float4*)d_in[0];
    const int*    seq_lens = (const int*)d_in[1];
    const int*    pK       = (n_in >= 3) ? (const int*)d_in[2] : nullptr;
    const int*    pS       = (n_in >= 4) ? (const int*)d_in[3] : nullptr;
    float4*       out      = (float4*)d_out;

    const int batch  = in_sizes[1];
    const int n_rows = out_size / 768;
    if (n_rows <= 0) return;

    const int grid = (n_rows + 3) / 4;
    pool_fused_kernel<<<grid, 384>>>(x, seq_lens, pK, pS, out, batch, n_rows);
}